// round 3
// baseline (speedup 1.0000x reference)
#include <cuda_runtime.h>
#include <math.h>

#define S   192
#define H   64
#define NH  8
#define SS  (S*S)    // 36864
#define SH  (S*H)    // 12288
#define SCALE 0.125f
#define NEGF (-1000000.0f)

// Output offsets (flattened concat of reference tuple: z, score, v_gated, M)
#define OFF_Z     0
#define OFF_SCORE 98304          // 8*192*64
#define OFF_VG    56721408       // + 8*192*192*192
#define OFF_M     75595776       // + 8*192*192*64

// ---- device scratch (no allocs allowed) ----
__device__ float g_qk[NH*SS];    // [n][t][q] = k2[t]·q[q]
__device__ float g_kk[NH*SS];    // [n][s][t] = k1[s]·k2[t]
__device__ float g_sv1[NH*SH];   // silu(v1)
__device__ float g_B[NH*SH];     // B[t,h] = v2[t,h] * sum_{s<=t} exp(scale*kk[s,t])*sv1[s,h]
__device__ float g_E[NH*S];      // E[t]   = sum_{s<=t} exp(scale*kk[s,t])
__device__ float g_Mkk[NH*S];    // max_{s<=t} scale*kk[s,t]
__device__ float g_w[NH*S*S];    // [n][t][q] = exp(scale*qk[t,q] - M0[q])
__device__ float g_L[NH*S];      // softmax denominator (no +0.01)

// ---------------------------------------------------------------------------
// K1: both Gram matrices. z<8: qk (head z), z>=8: kk (head z-8). 16x16 tiles.
__global__ void k_gram(const float* __restrict__ qm, const float* __restrict__ k1,
                       const float* __restrict__ k2) {
    int z = blockIdx.z;
    int n = z & 7;
    bool is_kk = z >= 8;
    const float* A = (is_kk ? k1 : k2) + n*SH;   // rows = t (qk) / s (kk)
    const float* B = (is_kk ? k2 : qm) + n*SH;   // rows = q (qk) / t (kk)
    float* C = (is_kk ? g_kk : g_qk) + n*SS;
    __shared__ float As[16][17], Bs[16][17];
    int ty = threadIdx.y, tx = threadIdx.x;
    int row = blockIdx.y*16 + ty;
    float acc = 0.f;
    #pragma unroll
    for (int k0 = 0; k0 < H; k0 += 16) {
        As[ty][tx] = A[row*H + k0 + tx];
        Bs[ty][tx] = B[(blockIdx.x*16 + ty)*H + k0 + tx];
        __syncthreads();
        #pragma unroll
        for (int k = 0; k < 16; k++) acc += As[ty][k]*Bs[tx][k];
        __syncthreads();
    }
    C[row*S + blockIdx.x*16 + tx] = acc;
}

// ---------------------------------------------------------------------------
// K2a: sv1 = silu(v1)
__global__ void k_silu(const float* __restrict__ v1) {
    int i = blockIdx.x*256 + threadIdx.x;
    float x = v1[i];
    g_sv1[i] = x / (1.f + __expf(-x));
}

// ---------------------------------------------------------------------------
// K2b: per (n,t): A/B[t,h], E[t], Mkk[t]. block = 64 threads (h).
__global__ void k_accumA(const float* __restrict__ v2) {
    int n = blockIdx.y, t = blockIdx.x, h = threadIdx.x;
    const float* kkcol = g_kk + n*SS + t;        // stride S over s
    __shared__ float sval[S];
    __shared__ float se[S];
    for (int s = h; s < S; s += 64) {
        float x = SCALE * kkcol[s*S];
        sval[s] = x;
        se[s]   = __expf(x);
    }
    __syncthreads();
    const float* sv1 = g_sv1 + n*SH;
    float acc = 0.f;
    #pragma unroll 4
    for (int s = 0; s <= t; s++) acc += se[s] * sv1[s*H + h];
    g_B[n*SH + t*H + h] = acc * v2[n*SH + t*H + h];
    if (h == 0) {
        float E = 0.f, mk = -1e30f;
        for (int s = 0; s <= t; s++) { E += se[s]; mk = fmaxf(mk, sval[s]); }
        g_E[n*S + t] = E;
        g_Mkk[n*S + t] = mk;
    }
}

// ---------------------------------------------------------------------------
// K3: per head: M0[q], L[q], w[t,q]; writes M output. block = 192 threads (q).
__global__ void k_stats(float* __restrict__ out) {
    int n = blockIdx.x, qi = threadIdx.x;
    const float* qkc = g_qk + n*SS;              // [t*S + q]
    const float* Mkk = g_Mkk + n*S;
    const float* E   = g_E + n*S;
    float m = -1e30f;
    #pragma unroll 4
    for (int t = 0; t <= qi; t++)
        m = fmaxf(m, SCALE*qkc[t*S + qi] + Mkk[t]);
    float* wc = g_w + n*SS;
    float L = 0.f;
    #pragma unroll 4
    for (int t = 0; t < S; t++) {
        float w = __expf(SCALE*qkc[t*S + qi] - m);
        wc[t*S + qi] = w;                        // only t<=qi consumed later
        if (t <= qi) L += w * E[t];
    }
    g_L[n*S + qi] = L;
    out[OFF_M + n*S + qi] = m + logf(L + 0.01f);
}

// ---------------------------------------------------------------------------
// K3b: z[q,h] = (1/L) sum_{t<=q} w[t,q]*B[t,h]. grid (q, n), block 64.
__global__ void k_z(float* __restrict__ out) {
    int n = blockIdx.y, qi = blockIdx.x, h = threadIdx.x;
    const float* wc = g_w + n*SS + qi;           // stride S over t (broadcast)
    const float* B  = g_B + n*SH;
    float acc = 0.f;
    #pragma unroll 4
    for (int t = 0; t <= qi; t++) acc += wc[t*S] * B[t*H + h];
    out[OFF_Z + (n*S + qi)*H + h] = acc / g_L[n*S + qi];
}

// ---------------------------------------------------------------------------
// K4 (big): score[n][s][t][q] = (s<=t && t<=q) ? kk[s,t]+qk[t,q] : -1e6.
// Block per (n,t): stages qk[t,:] and kk[:,t] in smem -> pure streaming STG.128.
__global__ void k_score(float* __restrict__ out) {
    int n = blockIdx.y, t = blockIdx.x;
    int tid = threadIdx.x;                       // 192 threads
    __shared__ __align__(16) float qkt[S];       // qk[t][q]
    __shared__ float kkc[S];                     // kk[s][t]
    qkt[tid] = g_qk[n*SS + t*S + tid];
    kkc[tid] = g_kk[n*SS + tid*S + t];
    __syncthreads();
    int qi4 = tid % 48;                          // float4 index along q
    int so  = tid / 48;                          // 0..3
    int q0  = qi4 * 4;
    float4 qv = *(const float4*)&qkt[q0];
    bool m0 = (t <= q0 + 0), m1 = (t <= q0 + 1),
         m2 = (t <= q0 + 2), m3 = (t <= q0 + 3);
    float* base = out + OFF_SCORE + n*(S*SS) + t*S;
    #pragma unroll 4
    for (int s = so; s < S; s += 4) {
        float kkv = kkc[s];
        bool sok = (s <= t);
        float4 v;
        v.x = (sok && m0) ? kkv + qv.x : NEGF;
        v.y = (sok && m1) ? kkv + qv.y : NEGF;
        v.z = (sok && m2) ? kkv + qv.z : NEGF;
        v.w = (sok && m3) ? kkv + qv.w : NEGF;
        *(float4*)&base[s*SS + q0] = v;
    }
}

// ---------------------------------------------------------------------------
// K5 (big): v_gated[n][s][t][h] = silu(v1)[s,h] * v2[t,h]  (unmasked).
// Block per (n,s): fully contiguous float4 stream.
__global__ void k_vgated(const float* __restrict__ v2, float* __restrict__ out) {
    int n = blockIdx.y, s = blockIdx.x;
    int tid = threadIdx.x;                       // 256 threads
    int h4 = tid % 16, to = tid / 16;            // 16 t-rows per iter
    const float4* sv1r = (const float4*)(g_sv1 + n*SH + s*H);
    float4 s1 = sv1r[h4];
    const float4* v2h = (const float4*)(v2 + n*SH);
    float4* ob = (float4*)(out + OFF_VG + (n*S + s)*SH);
    #pragma unroll 4
    for (int t = to; t < S; t += 16) {
        float4 v = v2h[t*16 + h4];
        float4 r;
        r.x = s1.x * v.x; r.y = s1.y * v.y;
        r.z = s1.z * v.z; r.w = s1.w * v.w;
        ob[t*16 + h4] = r;
    }
}

// ---------------------------------------------------------------------------
extern "C" void kernel_launch(void* const* d_in, const int* in_sizes, int n_in,
                              void* d_out, int out_size) {
    const float* q  = (const float*)d_in[0];
    const float* k1 = (const float*)d_in[1];
    const float* k2 = (const float*)d_in[2];
    const float* v1 = (const float*)d_in[3];
    const float* v2 = (const float*)d_in[4];
    float* out = (float*)d_out;

    k_gram  <<<dim3(12, 12, 16), dim3(16, 16)>>>(q, k1, k2);
    k_silu  <<<(NH*SH)/256, 256>>>(v1);
    k_accumA<<<dim3(S, NH), 64>>>(v2);
    k_stats <<<NH, S>>>(out);
    k_z     <<<dim3(S, NH), H>>>(out);
    k_score <<<dim3(S, NH), 192>>>(out);
    k_vgated<<<dim3(S, NH), 256>>>(v2, out);
}

// round 4
// speedup vs baseline: 1.6012x; 1.6012x over previous
#include <cuda_runtime.h>
#include <math.h>

#define S   192
#define H   64
#define NH  8
#define SS  (S*S)    // 36864
#define SH  (S*H)    // 12288
#define SCALE 0.125f
#define NEGF (-1000000.0f)

// Output offsets (flattened concat of reference tuple: z, score, v_gated, M)
#define OFF_Z     0
#define OFF_SCORE 98304          // 8*192*64
#define OFF_VG    56721408       // + 8*192*192*192
#define OFF_M     75595776       // + 8*192*192*64

// ---- device scratch (no allocs allowed) ----
__device__ float g_qk [NH*SS];   // [n][t][q] = k2[t]·q[q]   (row t contiguous, for k_score)
__device__ float g_qkT[NH*SS];   // [n][q][t]                (row q contiguous, for k_qz)
__device__ float g_kk [NH*SS];   // [n][s][t] = k1[s]·k2[t]
__device__ float g_sv1[NH*SH];   // silu(v1)
__device__ float g_B  [NH*SH];   // B[t,h] = v2[t,h] * sum_{s<=t} exp(scale*kk[s,t])*sv1[s,h]
__device__ float g_E  [NH*S];    // E[t]   = sum_{s<=t} exp(scale*kk[s,t])
__device__ float g_Mkk[NH*S];    // max_{s<=t} scale*kk[s,t]

// ---------------------------------------------------------------------------
// K1: both Gram matrices. z<8: qk (head z, also transposed copy); z>=8: kk.
__global__ void k_gram(const float* __restrict__ qm, const float* __restrict__ k1,
                       const float* __restrict__ k2) {
    int z = blockIdx.z;
    int n = z & 7;
    bool is_kk = z >= 8;
    const float* A = (is_kk ? k1 : k2) + n*SH;   // rows = t (qk) / s (kk)
    const float* B = (is_kk ? k2 : qm) + n*SH;   // rows = q (qk) / t (kk)
    float* C = (is_kk ? g_kk : g_qk) + n*SS;
    __shared__ float As[16][17], Bs[16][17];
    int ty = threadIdx.y, tx = threadIdx.x;
    int row = blockIdx.y*16 + ty;
    float acc = 0.f;
    #pragma unroll
    for (int k0 = 0; k0 < H; k0 += 16) {
        As[ty][tx] = A[row*H + k0 + tx];
        Bs[ty][tx] = B[(blockIdx.x*16 + ty)*H + k0 + tx];
        __syncthreads();
        #pragma unroll
        for (int k = 0; k < 16; k++) acc += As[ty][k]*Bs[tx][k];
        __syncthreads();
    }
    C[row*S + blockIdx.x*16 + tx] = acc;
    if (!is_kk) {
        // transposed copy through smem -> coalesced STG
        __syncthreads();
        As[ty][tx] = acc;
        __syncthreads();
        g_qkT[n*SS + (blockIdx.x*16 + ty)*S + blockIdx.y*16 + tx] = As[tx][ty];
    }
}

// ---------------------------------------------------------------------------
// K2a: sv1 = silu(v1)
__global__ void k_silu(const float* __restrict__ v1) {
    int i = blockIdx.x*256 + threadIdx.x;
    float x = v1[i];
    g_sv1[i] = x / (1.f + __expf(-x));
}

// ---------------------------------------------------------------------------
// K2b: per (n,t): B[t,h], E[t], Mkk[t]. block = 64 threads (h).
__global__ void k_accumA(const float* __restrict__ v2) {
    int n = blockIdx.y, t = blockIdx.x, h = threadIdx.x;
    const float* kkcol = g_kk + n*SS + t;        // stride S over s
    __shared__ float sval[S];
    __shared__ float se[S];
    for (int s = h; s < S; s += 64) {
        float x = SCALE * kkcol[s*S];
        sval[s] = x;
        se[s]   = __expf(x);
    }
    __syncthreads();
    const float* sv1 = g_sv1 + n*SH;
    float acc = 0.f;
    #pragma unroll 4
    for (int s = 0; s <= t; s++) acc += se[s] * sv1[s*H + h];
    g_B[n*SH + t*H + h] = acc * v2[n*SH + t*H + h];
    if (h == 0) {
        float E = 0.f, mk = -1e30f;
        for (int s = 0; s <= t; s++) { E += se[s]; mk = fmaxf(mk, sval[s]); }
        g_E[n*S + t] = E;
        g_Mkk[n*S + t] = mk;
    }
}

// ---------------------------------------------------------------------------
// K3 (fused stats + z): one block per (n,q), 192 threads (one per t).
//   M0 = max_{t<=q}(scale*qk[t,q] + Mkk[t])       (block max)
//   w[t] = exp(scale*qk - M0), masked -> 0        (smem)
//   L  = sum_{t<=q} w[t]*E[t]                     (block sum)
//   M  = M0 + log(L + 0.01)
//   z[q,h] = (1/L) sum_t w[t]*B[t,h]              (3 t-groups x 64 h)
__global__ void k_qz(float* __restrict__ out) {
    int n = blockIdx.y, q = blockIdx.x, t = threadIdx.x;
    __shared__ float sw[S];
    __shared__ float red[8];
    __shared__ float zpart[2][H];

    float x = SCALE * g_qkT[n*SS + q*S + t];      // coalesced
    float cand = (t <= q) ? x + g_Mkk[n*S + t] : -3.0e38f;
    // block max
    float v = cand;
    #pragma unroll
    for (int o = 16; o; o >>= 1) v = fmaxf(v, __shfl_xor_sync(0xffffffffu, v, o));
    if ((t & 31) == 0) red[t >> 5] = v;
    __syncthreads();
    if (t == 0) {
        float r = red[0];
        #pragma unroll
        for (int i = 1; i < 6; i++) r = fmaxf(r, red[i]);
        red[6] = r;
    }
    __syncthreads();
    float m = red[6];

    float w = (t <= q) ? __expf(x - m) : 0.f;
    sw[t] = w;
    float lt = w * g_E[n*S + t];                  // w==0 for masked t
    #pragma unroll
    for (int o = 16; o; o >>= 1) lt += __shfl_xor_sync(0xffffffffu, lt, o);
    if ((t & 31) == 0) red[t >> 5] = lt;
    __syncthreads();                               // also publishes sw[]
    if (t == 0) {
        float L = red[0];
        #pragma unroll
        for (int i = 1; i < 6; i++) L += red[i];
        red[7] = L;
        out[OFF_M + n*S + q] = m + logf(L + 0.01f);
    }
    __syncthreads();
    float L = red[7];

    // z contraction: h = t&63, group g = t>>6 handles t in [g*64, g*64+64)
    int h = t & 63, g = t >> 6;
    const float* B = g_B + n*SH + (g*64)*H + h;
    const float* wg = sw + g*64;
    float acc = 0.f;
    #pragma unroll 8
    for (int tt = 0; tt < 64; tt++) acc += wg[tt] * B[tt*H];
    if (g) zpart[g-1][h] = acc;
    __syncthreads();
    if (g == 0)
        out[OFF_Z + (n*S + q)*H + h] = (acc + zpart[0][h] + zpart[1][h]) / L;
}

// ---------------------------------------------------------------------------
// K4 (big): score[n][s][t][q] = (s<=t && t<=q) ? kk[s,t]+qk[t,q] : -1e6.
// Block per (n,t): stages qk[t,:] and kk[:,t] in smem -> pure streaming STG.128.
__global__ void k_score(float* __restrict__ out) {
    int n = blockIdx.y, t = blockIdx.x;
    int tid = threadIdx.x;                       // 192 threads
    __shared__ __align__(16) float qkt[S];       // qk[t][q]
    __shared__ float kkc[S];                     // kk[s][t]
    qkt[tid] = g_qk[n*SS + t*S + tid];
    kkc[tid] = g_kk[n*SS + tid*S + t];
    __syncthreads();
    int qi4 = tid % 48;                          // float4 index along q
    int so  = tid / 48;                          // 0..3
    int q0  = qi4 * 4;
    float4 qv = *(const float4*)&qkt[q0];
    bool m0 = (t <= q0 + 0), m1 = (t <= q0 + 1),
         m2 = (t <= q0 + 2), m3 = (t <= q0 + 3);
    float* base = out + OFF_SCORE + n*(S*SS) + t*S;
    #pragma unroll 4
    for (int s = so; s < S; s += 4) {
        float kkv = kkc[s];
        bool sok = (s <= t);
        float4 v;
        v.x = (sok && m0) ? kkv + qv.x : NEGF;
        v.y = (sok && m1) ? kkv + qv.y : NEGF;
        v.z = (sok && m2) ? kkv + qv.z : NEGF;
        v.w = (sok && m3) ? kkv + qv.w : NEGF;
        *(float4*)&base[s*SS + q0] = v;
    }
}

// ---------------------------------------------------------------------------
// K5 (big): v_gated[n][s][t][h] = silu(v1)[s,h] * v2[t,h]  (unmasked).
// Block per (n,s): fully contiguous float4 stream.
__global__ void k_vgated(const float* __restrict__ v2, float* __restrict__ out) {
    int n = blockIdx.y, s = blockIdx.x;
    int tid = threadIdx.x;                       // 256 threads
    int h4 = tid % 16, to = tid / 16;            // 16 t-rows per iter
    const float4* sv1r = (const float4*)(g_sv1 + n*SH + s*H);
    float4 s1 = sv1r[h4];
    const float4* v2h = (const float4*)(v2 + n*SH);
    float4* ob = (float4*)(out + OFF_VG + (n*S + s)*SH);
    #pragma unroll 4
    for (int t = to; t < S; t += 16) {
        float4 v = v2h[t*16 + h4];
        float4 r;
        r.x = s1.x * v.x; r.y = s1.y * v.y;
        r.z = s1.z * v.z; r.w = s1.w * v.w;
        ob[t*16 + h4] = r;
    }
}

// ---------------------------------------------------------------------------
extern "C" void kernel_launch(void* const* d_in, const int* in_sizes, int n_in,
                              void* d_out, int out_size) {
    const float* q  = (const float*)d_in[0];
    const float* k1 = (const float*)d_in[1];
    const float* k2 = (const float*)d_in[2];
    const float* v1 = (const float*)d_in[3];
    const float* v2 = (const float*)d_in[4];
    float* out = (float*)d_out;

    k_gram  <<<dim3(12, 12, 16), dim3(16, 16)>>>(q, k1, k2);
    k_silu  <<<(NH*SH)/256, 256>>>(v1);
    k_accumA<<<dim3(S, NH), 64>>>(v2);
    k_qz    <<<dim3(S, NH), S>>>(out);
    k_score <<<dim3(S, NH), 192>>>(out);
    k_vgated<<<dim3(S, NH), 256>>>(v2, out);
}